// round 8
// baseline (speedup 1.0000x reference)
#include <cuda_runtime.h>

// WeightedMseLoss: out = mean( (x - y)^2 * weight_table[round(y*100)] )
// Inputs: d_in[0]=x (f32, N), d_in[1]=y (f32, N), d_in[2]=weight_table (f32, 101)
// Output: 1 x f32 scalar.
//
// R8: 256-bit loads (ld.global.v8.f32, sm_100+) — half the LDG instructions,
// 2x bytes per outstanding load. 128-thread blocks (regs<=51, 10 blocks/SM),
// 1480 blocks = one wave, 2-deep unroll (4 x 32B loads in flight / thread),
// dual accumulators. R7's single-node atomic ending (no fence, no memset).

#define NBLOCKS    1480     // 148 SMs * 10 blocks -> one wave
#define NTHREADS   128
#define NUM_LEVELS 101

__device__ float        g_acc    = 0.0f;
__device__ unsigned int g_ticket = 0;

__device__ __forceinline__ void ldg_v8(const float* __restrict__ p, float r[8])
{
    asm volatile("ld.global.v8.f32 {%0,%1,%2,%3,%4,%5,%6,%7}, [%8];"
                 : "=f"(r[0]), "=f"(r[1]), "=f"(r[2]), "=f"(r[3]),
                   "=f"(r[4]), "=f"(r[5]), "=f"(r[6]), "=f"(r[7])
                 : "l"(p));
}

__global__ __launch_bounds__(NTHREADS, 10) void wmse_kernel(
    const float* __restrict__ x,
    const float* __restrict__ y,
    const float* __restrict__ wt,
    int n8,        // number of 8-float groups
    float invN,
    float* __restrict__ out)
{
    __shared__ float s_w[NUM_LEVELS];
    const int t = threadIdx.x;
    if (t < NUM_LEVELS) s_w[t] = wt[t];
    __syncthreads();

    const int stride = gridDim.x * blockDim.x;
    int i = blockIdx.x * blockDim.x + t;

    float acc0 = 0.0f, acc1 = 0.0f;

    // 2-deep unroll: 4 independent 32B loads in flight per iteration
    for (; i + stride < n8; i += 2 * stride) {
        float xa[8], ya[8], xb[8], yb[8];
        ldg_v8(x + (size_t)i * 8,            xa);
        ldg_v8(y + (size_t)i * 8,            ya);
        ldg_v8(x + (size_t)(i + stride) * 8, xb);
        ldg_v8(y + (size_t)(i + stride) * 8, yb);

        #pragma unroll
        for (int k = 0; k < 8; k++) {
            int   idx = __float2int_rn(ya[k] * 100.0f);
            float d   = xa[k] - ya[k];
            acc0 = fmaf(d * d, s_w[idx], acc0);
        }
        #pragma unroll
        for (int k = 0; k < 8; k++) {
            int   idx = __float2int_rn(yb[k] * 100.0f);
            float d   = xb[k] - yb[k];
            acc1 = fmaf(d * d, s_w[idx], acc1);
        }
    }
    // remainder (at most one group per thread)
    for (; i < n8; i += stride) {
        float xv[8], yv[8];
        ldg_v8(x + (size_t)i * 8, xv);
        ldg_v8(y + (size_t)i * 8, yv);
        #pragma unroll
        for (int k = 0; k < 8; k++) {
            int   idx = __float2int_rn(yv[k] * 100.0f);
            float d   = xv[k] - yv[k];
            acc0 = fmaf(d * d, s_w[idx], acc0);
        }
    }

    float acc = acc0 + acc1;

    // block reduce (128 threads = 4 warps)
    #pragma unroll
    for (int o = 16; o > 0; o >>= 1)
        acc += __shfl_down_sync(0xffffffffu, acc, o);

    __shared__ float s_sum[NTHREADS / 32];
    if ((t & 31) == 0) s_sum[t >> 5] = acc;
    __syncthreads();

    if (t < 32) {
        float v = (t < NTHREADS / 32) ? s_sum[t] : 0.0f;
        #pragma unroll
        for (int o = 2; o > 0; o >>= 1)
            v += __shfl_down_sync(0xffffffffu, v, o);
        if (t == 0) {
            atomicAdd(&g_acc, v);
            unsigned int old;
            asm volatile("atom.add.acq_rel.gpu.global.u32 %0, [%1], 1;"
                         : "=r"(old) : "l"(&g_ticket) : "memory");
            if (old == (unsigned int)(NBLOCKS - 1)) {
                out[0] = g_acc * invN;
                g_acc    = 0.0f;   // reset for next graph replay
                g_ticket = 0u;
            }
        }
    }
}

extern "C" void kernel_launch(void* const* d_in, const int* in_sizes, int n_in,
                              void* d_out, int out_size)
{
    const float* x  = (const float*)d_in[0];
    const float* y  = (const float*)d_in[1];
    const float* wt = (const float*)d_in[2];
    float* out = (float*)d_out;

    const int n  = in_sizes[0];
    const int n8 = n >> 3;  // N = 2^24, divisible by 8

    wmse_kernel<<<NBLOCKS, NTHREADS>>>(x, y, wt, n8, 1.0f / (float)n, out);
}